// round 7
// baseline (speedup 1.0000x reference)
#include <cuda_runtime.h>
#include <cuda_bf16.h>
#include <cstdint>

// ---------------------------------------------------------------------------
// Problem constants
// ---------------------------------------------------------------------------
#define BB 4
#define CC 2048
#define EE 1024
#define HH 16
#define DD 64
#define MM (BB * CC)          // 8192 rows
#define FF (4 * EE)           // 4096 mlp hidden
#define KVS 2048              // fused K|V row stride

// ---------------------------------------------------------------------------
// Scratch
// ---------------------------------------------------------------------------
#define MB (1ull << 20)
__device__ __align__(256) unsigned char g_scratch[364 * MB];

#define OFF_NH    (0 * MB)
#define OFF_NL    (16 * MB)
#define OFF_HH    (32 * MB)
#define OFF_HL    (48 * MB)
#define OFF_QH    (64 * MB)
#define OFF_QL    (80 * MB)
#define OFF_KVH   (96 * MB)     // [MM, 2048] bf16  (K cols 0-1023, V 1024-2047)
#define OFF_KVL   (128 * MB)
#define OFF_OUTB  (160 * MB)
#define OFF_M1H   (192 * MB)
#define OFF_M1L   (256 * MB)
#define OFF_WQH   (320 * MB)
#define OFF_WQL   (322 * MB)
#define OFF_WKVH  (324 * MB)    // [2048, 1024] bf16
#define OFF_WKVL  (328 * MB)
#define OFF_W1H   (332 * MB)
#define OFF_W1L   (340 * MB)
#define OFF_W2H   (348 * MB)
#define OFF_W2L   (356 * MB)

// ---------------------------------------------------------------------------
// PTX helpers (baseline compute_103 only — no 'a' features)
// ---------------------------------------------------------------------------
__device__ __forceinline__ uint32_t smem_u32(const void* p) {
    uint32_t a;
    asm("{ .reg .u64 t; cvta.to.shared.u64 t, %1; cvt.u32.u64 %0, t; }"
        : "=r"(a) : "l"(p));
    return a;
}
__device__ __forceinline__ void cpa16(uint32_t d, const void* s) {
    asm volatile("cp.async.cg.shared.global [%0], [%1], 16;" :: "r"(d), "l"(s));
}
#define CP_COMMIT() asm volatile("cp.async.commit_group;" ::: "memory")

__device__ __forceinline__ void ldsm4(uint32_t* r, uint32_t addr) {
    asm volatile("ldmatrix.sync.aligned.m8n8.x4.shared.b16 {%0,%1,%2,%3}, [%4];"
                 : "=r"(r[0]), "=r"(r[1]), "=r"(r[2]), "=r"(r[3]) : "r"(addr));
}
__device__ __forceinline__ void ldsm4t(uint32_t* r, uint32_t addr) {
    asm volatile("ldmatrix.sync.aligned.m8n8.x4.trans.shared.b16 {%0,%1,%2,%3}, [%4];"
                 : "=r"(r[0]), "=r"(r[1]), "=r"(r[2]), "=r"(r[3]) : "r"(addr));
}
__device__ __forceinline__ void mma16816(float* c, const uint32_t* a,
                                         const uint32_t* b) {
    asm volatile(
        "mma.sync.aligned.m16n8k16.row.col.f32.bf16.bf16.f32 "
        "{%0,%1,%2,%3}, {%4,%5,%6,%7}, {%8,%9}, {%0,%1,%2,%3};"
        : "+f"(c[0]), "+f"(c[1]), "+f"(c[2]), "+f"(c[3])
        : "r"(a[0]), "r"(a[1]), "r"(a[2]), "r"(a[3]), "r"(b[0]), "r"(b[1]));
}

__device__ __forceinline__ void split2(float a, float b, uint32_t& hi, uint32_t& lo) {
    const __nv_bfloat16 ha = __float2bfloat16(a), hb = __float2bfloat16(b);
    __nv_bfloat162 th = __halves2bfloat162(ha, hb);
    hi = *reinterpret_cast<uint32_t*>(&th);
    const float ra = a - __bfloat162float(ha);
    const float rb = b - __bfloat162float(hb);
    __nv_bfloat162 tl = __halves2bfloat162(__float2bfloat16(ra), __float2bfloat16(rb));
    lo = *reinterpret_cast<uint32_t*>(&tl);
}

// ---------------------------------------------------------------------------
// Weight transpose + bf16 hi/lo split:  W[K,N] fp32  ->  Th/Tl [N,K] bf16
// ---------------------------------------------------------------------------
__global__ __launch_bounds__(256) void tsplit_kernel(
    const float* __restrict__ W, __nv_bfloat16* __restrict__ Th,
    __nv_bfloat16* __restrict__ Tl, int K, int N)
{
    __shared__ float t[32][33];
    const int n0 = blockIdx.x * 32, k0 = blockIdx.y * 32;
    const int tx = threadIdx.x & 31, ty = threadIdx.x >> 5;
    #pragma unroll
    for (int j = 0; j < 32; j += 8)
        t[ty + j][tx] = W[(size_t)(k0 + ty + j) * N + n0 + tx];
    __syncthreads();
    #pragma unroll
    for (int j = 0; j < 32; j += 8) {
        const float v = t[tx][ty + j];
        const __nv_bfloat16 h = __float2bfloat16(v);
        const __nv_bfloat16 l = __float2bfloat16(v - __bfloat162float(h));
        const size_t o = (size_t)(n0 + ty + j) * K + k0 + tx;
        Th[o] = h; Tl[o] = l;
    }
}

// ---------------------------------------------------------------------------
// LayerNorm -> bf16 hi/lo
// ---------------------------------------------------------------------------
__global__ __launch_bounds__(256) void ln_kernel(
    const float* __restrict__ x, const float* __restrict__ gamma,
    const float* __restrict__ beta, __nv_bfloat16* __restrict__ yh,
    __nv_bfloat16* __restrict__ yl)
{
    const int row = blockIdx.x;
    const int t = threadIdx.x;
    const float4 v = ((const float4*)(x + (size_t)row * EE))[t];
    float s  = v.x + v.y + v.z + v.w;
    float s2 = fmaf(v.x, v.x, fmaf(v.y, v.y, fmaf(v.z, v.z, v.w * v.w)));
    #pragma unroll
    for (int o = 16; o > 0; o >>= 1) {
        s  += __shfl_xor_sync(0xffffffffu, s, o);
        s2 += __shfl_xor_sync(0xffffffffu, s2, o);
    }
    __shared__ float rs[8], rs2[8];
    __shared__ float sstat[2];
    if ((t & 31) == 0) { rs[t >> 5] = s; rs2[t >> 5] = s2; }
    __syncthreads();
    if (t == 0) {
        float S = 0.f, S2 = 0.f;
        #pragma unroll
        for (int w = 0; w < 8; w++) { S += rs[w]; S2 += rs2[w]; }
        const float mean = S * (1.0f / EE);
        const float var  = S2 * (1.0f / EE) - mean * mean;
        sstat[0] = mean;
        sstat[1] = rsqrtf(var + 1e-5f);
    }
    __syncthreads();
    const float mean = sstat[0], rstd = sstat[1];
    const float4 gv = ((const float4*)gamma)[t];
    const float4 bv = ((const float4*)beta)[t];
    float o0 = (v.x - mean) * rstd * gv.x + bv.x;
    float o1 = (v.y - mean) * rstd * gv.y + bv.y;
    float o2 = (v.z - mean) * rstd * gv.z + bv.z;
    float o3 = (v.w - mean) * rstd * gv.w + bv.w;
    uint32_t h0, l0, h1, l1;
    split2(o0, o1, h0, l0);
    split2(o2, o3, h1, l1);
    uint32_t* ph = (uint32_t*)(yh + (size_t)row * EE + 4 * t);
    uint32_t* pl = (uint32_t*)(yl + (size_t)row * EE + 4 * t);
    ph[0] = h0; ph[1] = h1;
    pl[0] = l0; pl[1] = l1;
}

// ---------------------------------------------------------------------------
// mma.sync bf16x3 GEMM, 128x128 tile, 2-stage cp.async, 2 CTAs/SM.
// Pass-outer MMA ordering: 16 independent MMAs between accumulator reuse.
// ---------------------------------------------------------------------------
#define ROWB 80u
#define MATB 10240u
#define STGB 40960u
#define GSM_BYTES (2 * 40960)    // 81920

__global__ __launch_bounds__(256, 2) void gemm_tc(
    const __nv_bfloat16* __restrict__ Ah, const __nv_bfloat16* __restrict__ Al,
    const __nv_bfloat16* __restrict__ Bh, const __nv_bfloat16* __restrict__ Bl,
    const float* __restrict__ bias, const float* __restrict__ bias2, int nsplit,
    const float* __restrict__ res,
    float* __restrict__ Cf, __nv_bfloat16* __restrict__ Ch,
    __nv_bfloat16* __restrict__ Cl, int M, int N, int K, int relu, float oscale)
{
    extern __shared__ unsigned char smem[];
    const uint32_t sbase = smem_u32(smem);
    const int tid = threadIdx.x;
    const int lane = tid & 31, wid = tid >> 5;
    const int wm = wid >> 2, wn = wid & 3;
    const int row0 = blockIdx.y * 128, col0 = blockIdx.x * 128;

    const __nv_bfloat16* gAh = Ah + (size_t)row0 * K;
    const __nv_bfloat16* gAl = Al + (size_t)row0 * K;
    const __nv_bfloat16* gBh = Bh + (size_t)col0 * K;
    const __nv_bfloat16* gBl = Bl + (size_t)col0 * K;
    const int nch = K >> 5;

    float acc[4][4][4];
    #pragma unroll
    for (int a = 0; a < 4; a++)
        #pragma unroll
        for (int b = 0; b < 4; b++)
            #pragma unroll
            for (int c = 0; c < 4; c++) acc[a][b][c] = 0.f;

    const uint32_t a_base = (uint32_t)(wm * 64 + (lane & 15)) * ROWB +
                            (((lane >> 4) << 3) << 1);
    const uint32_t b_base = (uint32_t)(wn * 32 + ((lane >> 4) << 3) + (lane & 7)) * ROWB +
                            ((((lane >> 3) & 1) << 3) << 1);

    auto load_chunk = [&](int ch, int s) {
        const int k0 = ch << 5;
        const uint32_t st = sbase + s * STGB;
        #pragma unroll
        for (int i = 0; i < 8; i++) {
            const __nv_bfloat16* src = (i < 2) ? gAh : (i < 4) ? gAl
                                     : (i < 6) ? gBh : gBl;
            const int rem = ((i & 1) << 8) + tid;
            const int r = rem >> 2, g = rem & 3;
            cpa16(st + (uint32_t)(i >> 1) * MATB + (uint32_t)r * ROWB + g * 16u,
                  src + (size_t)r * K + k0 + g * 8);
        }
    };

    auto compute_chunk = [&](int s) {
        const uint32_t st = sbase + s * STGB;
        #pragma unroll
        for (int ks = 0; ks < 32; ks += 16) {
            uint32_t aH[4][4], aL[4][4], bH[2][4], bL[2][4];
            const uint32_t ao = a_base + (ks << 1);
            #pragma unroll
            for (int mi = 0; mi < 4; mi++) {
                ldsm4(aH[mi], st + ao + (uint32_t)mi * 16 * ROWB);
                ldsm4(aL[mi], st + MATB + ao + (uint32_t)mi * 16 * ROWB);
            }
            const uint32_t bo = b_base + (ks << 1);
            #pragma unroll
            for (int p = 0; p < 2; p++) {
                ldsm4(bH[p], st + 2 * MATB + bo + (uint32_t)p * 16 * ROWB);
                ldsm4(bL[p], st + 3 * MATB + bo + (uint32_t)p * 16 * ROWB);
            }
            // pass 0: Ah * Bh — 16 independent MMAs
            #pragma unroll
            for (int mi = 0; mi < 4; mi++)
                #pragma unroll
                for (int p = 0; p < 2; p++)
                    #pragma unroll
                    for (int h = 0; h < 2; h++)
                        mma16816(acc[mi][p * 2 + h], aH[mi], &bH[p][h * 2]);
            // pass 1: Ah * Bl
            #pragma unroll
            for (int mi = 0; mi < 4; mi++)
                #pragma unroll
                for (int p = 0; p < 2; p++)
                    #pragma unroll
                    for (int h = 0; h < 2; h++)
                        mma16816(acc[mi][p * 2 + h], aH[mi], &bL[p][h * 2]);
            // pass 2: Al * Bh
            #pragma unroll
            for (int mi = 0; mi < 4; mi++)
                #pragma unroll
                for (int p = 0; p < 2; p++)
                    #pragma unroll
                    for (int h = 0; h < 2; h++)
                        mma16816(acc[mi][p * 2 + h], aL[mi], &bH[p][h * 2]);
        }
    };

    load_chunk(0, 0); CP_COMMIT();
    load_chunk(1, 1); CP_COMMIT();

    for (int ch = 0; ch < nch; ch++) {
        asm volatile("cp.async.wait_group 1;" ::: "memory");
        __syncthreads();
        compute_chunk(ch & 1);
        __syncthreads();
        if (ch + 2 < nch) load_chunk(ch + 2, ch & 1);
        CP_COMMIT();
    }
    asm volatile("cp.async.wait_group 0;" ::: "memory");

    // ---------------- epilogue ----------------
    const float* effb = (bias2 && col0 >= nsplit) ? (bias2 - nsplit) : bias;
    const int tr = lane >> 2, tc = (lane & 3) << 1;
    #pragma unroll
    for (int mi = 0; mi < 4; mi++) {
        #pragma unroll
        for (int ni = 0; ni < 4; ni++) {
            const int col = col0 + wn * 32 + ni * 8 + tc;
            const float2 bb = *(const float2*)&effb[col];
            #pragma unroll
            for (int hr = 0; hr < 2; hr++) {
                const int row = row0 + wm * 64 + mi * 16 + tr + hr * 8;
                float v0 = acc[mi][ni][hr * 2 + 0] + bb.x;
                float v1 = acc[mi][ni][hr * 2 + 1] + bb.y;
                if (relu) { v0 = fmaxf(v0, 0.f); v1 = fmaxf(v1, 0.f); }
                v0 *= oscale; v1 *= oscale;
                const size_t goff = (size_t)row * N + col;
                if (Cf) {
                    if (res) {
                        const float2 rv = *(const float2*)&res[goff];
                        v0 += rv.x; v1 += rv.y;
                    }
                    *(float2*)&Cf[goff] = make_float2(v0, v1);
                } else {
                    uint32_t hp, lp;
                    split2(v0, v1, hp, lp);
                    *(uint32_t*)&Ch[goff] = hp;
                    *(uint32_t*)&Cl[goff] = lp;
                }
            }
        }
    }
}

// ---------------------------------------------------------------------------
// Tensor-core flash attention (causal), bf16x3 precision.
// BM=128, BN=64, 256 threads (8 warps, warp tile 16x64). Q pre-scaled 1/8.
// np-paired, pass-outer MMA ordering (dependency spacing 4).
// ---------------------------------------------------------------------------
#define AR 144u                   // bytes per smem row (64 bf16 + 8 pad)
#define AQMAT 18432u              // 128 rows * 144B
#define AKMAT 9216u               // 64 rows * 144B
#define ASTG (4 * AKMAT)          // Kh,Kl,Vh,Vl per stage = 36864
#define ATTN_SMEM (2 * AQMAT + 2 * ASTG)   // 110592

__global__ __launch_bounds__(256) void attn_mma(
    const __nv_bfloat16* __restrict__ Qh, const __nv_bfloat16* __restrict__ Ql,
    const __nv_bfloat16* __restrict__ KVh, const __nv_bfloat16* __restrict__ KVl,
    const float* __restrict__ inp, float* __restrict__ Out)
{
    extern __shared__ unsigned char smem[];
    const uint32_t sbase = smem_u32(smem);
    const int tid = threadIdx.x, lane = tid & 31, w = tid >> 5;
    const int qt = blockIdx.x, h = blockIdx.y, b = blockIdx.z;
    const int q0 = qt * 128;
    const int nt = 2 * qt + 2;                 // kv tiles (64 rows each)

    // ---- load Q tile (128 rows, hi+lo) ----
    {
        const size_t ro = (size_t)(b * CC + q0) * EE + (size_t)h * 64;
        #pragma unroll
        for (int i = 0; i < 4; i++) {
            const int idx = i * 256 + tid;
            const int r = idx >> 3, g = idx & 7;
            const uint32_t d = sbase + (uint32_t)r * AR + g * 16u;
            const size_t so = ro + (size_t)r * EE + g * 8;
            cpa16(d, Qh + so);
            cpa16(d + AQMAT, Ql + so);
        }
    }
    CP_COMMIT();

    const size_t kvbase = (size_t)(b * CC) * KVS + (size_t)h * 64;
    auto load_kv = [&](int t, int s) {
        const uint32_t st = sbase + 2 * AQMAT + (uint32_t)s * ASTG;
        const size_t ro = kvbase + (size_t)(t * 64) * KVS;
        #pragma unroll
        for (int i = 0; i < 2; i++) {
            const int idx = i * 256 + tid;
            const int r = idx >> 3, g = idx & 7;
            const uint32_t d = st + (uint32_t)r * AR + g * 16u;
            const size_t so = ro + (size_t)r * KVS + g * 8;
            cpa16(d, KVh + so);
            cpa16(d + AKMAT, KVl + so);
            cpa16(d + 2 * AKMAT, KVh + so + 1024);
            cpa16(d + 3 * AKMAT, KVl + so + 1024);
        }
    };
    load_kv(0, 0); CP_COMMIT();

    float O[8][4];
    #pragma unroll
    for (int n = 0; n < 8; n++)
        #pragma unroll
        for (int j = 0; j < 4; j++) O[n][j] = 0.f;
    float m_lo = -1e30f, m_hi = -1e30f, l_lo = 0.f, l_hi = 0.f;
    uint32_t qHf[4][4], qLf[4][4];

    const int rowl = w * 16 + (lane >> 2);     // local q row (lo); hi = +8
    const int c0 = (lane & 3) << 1;

    for (int t = 0; t < nt; t++) {
        if (t + 1 < nt) load_kv(t + 1, (t + 1) & 1);
        CP_COMMIT();
        asm volatile("cp.async.wait_group 1;" ::: "memory");
        __syncthreads();

        const uint32_t sK = sbase + 2 * AQMAT + (uint32_t)(t & 1) * ASTG;
        const uint32_t sV = sK + 2 * AKMAT;

        if (t == 0) {
            const uint32_t qa = sbase + (uint32_t)(w * 16 + (lane & 15)) * AR +
                                (((lane >> 4) << 3) << 1);
            #pragma unroll
            for (int ks = 0; ks < 4; ks++) {
                ldsm4(qHf[ks], qa + ks * 32);
                ldsm4(qLf[ks], qa + AQMAT + ks * 32);
            }
        }

        // ---- S = Q @ K^T (3-pass, np-paired pass-outer) ----
        float S[8][4];
        #pragma unroll
        for (int n = 0; n < 8; n++)
            #pragma unroll
            for (int j = 0; j < 4; j++) S[n][j] = 0.f;

        #pragma unroll
        for (int ks = 0; ks < 4; ks++) {
            #pragma unroll
            for (int np = 0; np < 4; np += 2) {
                const uint32_t kb0 = sK +
                    (uint32_t)(np * 16 + ((lane >> 4) << 3) + (lane & 7)) * AR +
                    ((((lane >> 3) & 1) << 3) << 1) + ks * 32;
                const uint32_t kb1 = kb0 + 16 * AR;
                uint32_t bh0[4], bl0[4], bh1[4], bl1[4];
                ldsm4(bh0, kb0); ldsm4(bl0, kb0 + AKMAT);
                ldsm4(bh1, kb1); ldsm4(bl1, kb1 + AKMAT);
                #pragma unroll
                for (int h2 = 0; h2 < 2; h2++) {
                    mma16816(S[np * 2 + h2],       qHf[ks], &bh0[h2 * 2]);
                    mma16816(S[(np + 1) * 2 + h2], qHf[ks], &bh1[h2 * 2]);
                }
                #pragma unroll
                for (int h2 = 0; h2 < 2; h2++) {
                    mma16816(S[np * 2 + h2],       qHf[ks], &bl0[h2 * 2]);
                    mma16816(S[(np + 1) * 2 + h2], qHf[ks], &bl1[h2 * 2]);
                }
                #pragma unroll
                for (int h2 = 0; h2 < 2; h2++) {
                    mma16816(S[np * 2 + h2],       qLf[ks], &bh0[h2 * 2]);
                    mma16816(S[(np + 1) * 2 + h2], qLf[ks], &bh1[h2 * 2]);
                }
            }
        }

        // ---- causal mask (only tiles overlapping/above the diagonal) ----
        if (t >= 2 * qt) {
            const int colg0 = t * 64;
            const int rg_lo = q0 + rowl, rg_hi = rg_lo + 8;
            #pragma unroll
            for (int n = 0; n < 8; n++) {
                const int col = colg0 + n * 8 + c0;
                if (col > rg_lo)     S[n][0] = -1e30f;
                if (col + 1 > rg_lo) S[n][1] = -1e30f;
                if (col > rg_hi)     S[n][2] = -1e30f;
                if (col + 1 > rg_hi) S[n][3] = -1e30f;
            }
        }

        // ---- online softmax ----
        float mx0 = -1e30f, mx1 = -1e30f;
        #pragma unroll
        for (int n = 0; n < 8; n++) {
            mx0 = fmaxf(mx0, fmaxf(S[n][0], S[n][1]));
            mx1 = fmaxf(mx1, fmaxf(S[n][2], S[n][3]));
        }
        mx0 = fmaxf(mx0, __shfl_xor_sync(0xffffffffu, mx0, 1));
        mx0 = fmaxf(mx0, __shfl_xor_sync(0xffffffffu, mx0, 2));
        mx1 = fmaxf(mx1, __shfl_xor_sync(0xffffffffu, mx1, 1));
        mx1 = fmaxf(mx1, __shfl_xor_sync(0xffffffffu, mx1, 2));
        const float mn0 = fmaxf(m_lo, mx0), mn1 = fmaxf(m_hi, mx1);
        const float cr0 = __expf(m_lo - mn0), cr1 = __expf(m_hi - mn1);
        float s0 = 0.f, s1 = 0.f;
        #pragma unroll
        for (int n = 0; n < 8; n++) {
            S[n][0] = __expf(S[n][0] - mn0); s0 += S[n][0];
            S[n][1] = __expf(S[n][1] - mn0); s0 += S[n][1];
            S[n][2] = __expf(S[n][2] - mn1); s1 += S[n][2];
            S[n][3] = __expf(S[n][3] - mn1); s1 += S[n][3];
        }
        s0 += __shfl_xor_sync(0xffffffffu, s0, 1);
        s0 += __shfl_xor_sync(0xffffffffu, s0, 2);
        s1 += __shfl_xor_sync(0xffffffffu, s1, 1);
        s1 += __shfl_xor_sync(0xffffffffu, s1, 2);
        l_lo = l_lo * cr0 + s0; l_hi = l_hi * cr1 + s1;
        m_lo = mn0; m_hi = mn1;
        #pragma unroll
        for (int n = 0; n < 8; n++) {
            O[n][0] *= cr0; O[n][1] *= cr0;
            O[n][2] *= cr1; O[n][3] *= cr1;
        }

        // ---- P -> bf16 hi/lo A-fragments (C-frag reuse) ----
        uint32_t pH[4][4], pL[4][4];
        #pragma unroll
        for (int kk = 0; kk < 4; kk++) {
            split2(S[2 * kk][0],     S[2 * kk][1],     pH[kk][0], pL[kk][0]);
            split2(S[2 * kk][2],     S[2 * kk][3],     pH[kk][1], pL[kk][1]);
            split2(S[2 * kk + 1][0], S[2 * kk + 1][1], pH[kk][2], pL[kk][2]);
            split2(S[2 * kk + 1][2], S[2 * kk + 1][3], pH[kk][3], pL[kk][3]);
        }

        // ---- O += P @ V (3-pass, np-paired pass-outer, ldmatrix.trans) ----
        #pragma unroll
        for (int kk = 0; kk < 4; kk++) {
            #pragma unroll
            for (int np = 0; np < 4; np += 2) {
                const uint32_t va0 = sV +
                    (uint32_t)(kk * 16 + ((lane >> 3) & 1) * 8 + (lane & 7)) * AR +
                    ((np * 16 + ((lane >> 4) << 3)) << 1);
                const uint32_t va1 = va0 + 32;
                uint32_t vh0[4], vl0[4], vh1[4], vl1[4];
                ldsm4t(vh0, va0); ldsm4t(vl0, va0 + AKMAT);
                ldsm4t(vh1, va1); ldsm4t(vl1, va1 + AKMAT);
                #pragma unroll
                for (int h2 = 0; h2 < 2; h2++) {
                    mma16816(O[np * 2 + h2],       pH[kk], &vh0[h2 * 2]);
                    mma16816(O[(np + 1) * 2 + h2], pH[kk], &vh1[h2 * 2]);
                }
                #pragma unroll
                for (int h2 = 0; h2 < 2; h2++) {
                    mma16816(O[np * 2 + h2],       pH[kk], &vl0[h2 * 2]);
                    mma16816(O[(np + 1) * 2 + h2], pH[kk], &vl1[h2 * 2]);
                }
                #pragma unroll
                for (int h2 = 0; h2 < 2; h2++) {
                    mma16816(O[np * 2 + h2],       pL[kk], &vh0[h2 * 2]);
                    mma16816(O[(np + 1) * 2 + h2], pL[kk], &vh1[h2 * 2]);
                }
            }
        }
        __syncthreads();
    }

    // ---- finalize: /l, add residual, store fp32 ----
    const float inv0 = 1.0f / l_lo, inv1 = 1.0f / l_hi;
    const int gr0 = b * CC + q0 + rowl;
    #pragma unroll
    for (int n = 0; n < 8; n++) {
        const int col = h * 64 + n * 8 + c0;
        const size_t o0 = (size_t)gr0 * EE + col;
        const size_t o1 = o0 + (size_t)8 * EE;
        const float2 i0 = *(const float2*)&inp[o0];
        const float2 i1 = *(const float2*)&inp[o1];
        *(float2*)&Out[o0] = make_float2(i0.x + O[n][0] * inv0,
                                         i0.y + O[n][1] * inv0);
        *(float2*)&Out[o1] = make_float2(i1.x + O[n][2] * inv1,
                                         i1.y + O[n][3] * inv1);
    }
}

// ---------------------------------------------------------------------------
// kernel_launch
// ---------------------------------------------------------------------------
extern "C" void kernel_launch(void* const* d_in, const int* in_sizes, int n_in,
                              void* d_out, int out_size)
{
    const float* inputs = (const float*)d_in[0];
    const float* Wq     = (const float*)d_in[1];
    const float* bq     = (const float*)d_in[2];
    const float* Wk     = (const float*)d_in[3];
    const float* bk     = (const float*)d_in[4];
    const float* Wv     = (const float*)d_in[5];
    const float* bv     = (const float*)d_in[6];
    const float* g1     = (const float*)d_in[7];
    const float* beta1  = (const float*)d_in[8];
    const float* g2     = (const float*)d_in[9];
    const float* beta2  = (const float*)d_in[10];
    const float* W1     = (const float*)d_in[11];
    const float* bm1    = (const float*)d_in[12];
    const float* W2     = (const float*)d_in[13];
    const float* bm2    = (const float*)d_in[14];
    float* out = (float*)d_out;

    unsigned char* base = nullptr;
    cudaGetSymbolAddress((void**)&base, g_scratch);
    __nv_bfloat16* nh    = (__nv_bfloat16*)(base + OFF_NH);
    __nv_bfloat16* nl    = (__nv_bfloat16*)(base + OFF_NL);
    __nv_bfloat16* hh    = (__nv_bfloat16*)(base + OFF_HH);
    __nv_bfloat16* hl    = (__nv_bfloat16*)(base + OFF_HL);
    __nv_bfloat16* qh    = (__nv_bfloat16*)(base + OFF_QH);
    __nv_bfloat16* ql    = (__nv_bfloat16*)(base + OFF_QL);
    __nv_bfloat16* kvh   = (__nv_bfloat16*)(base + OFF_KVH);
    __nv_bfloat16* kvl   = (__nv_bfloat16*)(base + OFF_KVL);
    float* outbuf        = (float*)(base + OFF_OUTB);
    __nv_bfloat16* m1h   = (__nv_bfloat16*)(base + OFF_M1H);
    __nv_bfloat16* m1l   = (__nv_bfloat16*)(base + OFF_M1L);
    __nv_bfloat16* WqTh  = (__nv_bfloat16*)(base + OFF_WQH);
    __nv_bfloat16* WqTl  = (__nv_bfloat16*)(base + OFF_WQL);
    __nv_bfloat16* WkvTh = (__nv_bfloat16*)(base + OFF_WKVH);
    __nv_bfloat16* WkvTl = (__nv_bfloat16*)(base + OFF_WKVL);
    __nv_bfloat16* W1Th  = (__nv_bfloat16*)(base + OFF_W1H);
    __nv_bfloat16* W1Tl  = (__nv_bfloat16*)(base + OFF_W1L);
    __nv_bfloat16* W2Th  = (__nv_bfloat16*)(base + OFF_W2H);
    __nv_bfloat16* W2Tl  = (__nv_bfloat16*)(base + OFF_W2L);

    cudaFuncSetAttribute(gemm_tc, cudaFuncAttributeMaxDynamicSharedMemorySize,
                         GSM_BYTES);
    cudaFuncSetAttribute(attn_mma, cudaFuncAttributeMaxDynamicSharedMemorySize,
                         ATTN_SMEM);

    // Launch order keeps index 3 == gemm_tc (Q proj) for ncu capture.
    // 0: Wq prep
    tsplit_kernel<<<dim3(EE / 32, EE / 32), 256>>>(Wq, WqTh, WqTl, EE, EE);
    // 1: LN1 -> bf16 pair
    ln_kernel<<<MM, 256>>>(inputs, g1, beta1, nh, nl);
    // 2: Wk prep (rows 0..1023 of fused)
    tsplit_kernel<<<dim3(EE / 32, EE / 32), 256>>>(Wk, WkvTh, WkvTl, EE, EE);
    // 3: Q projection (profiled)
    gemm_tc<<<dim3(EE / 128, MM / 128), 256, GSM_BYTES>>>(
        nh, nl, WqTh, WqTl, bq, nullptr, 0, nullptr, nullptr,
        qh, ql, MM, EE, EE, 0, 0.125f);
    // 4: Wv prep (rows 1024..2047 of fused)
    tsplit_kernel<<<dim3(EE / 32, EE / 32), 256>>>(
        Wv, WkvTh + (size_t)1024 * EE, WkvTl + (size_t)1024 * EE, EE, EE);
    // 5: fused K|V projection (N=2048)
    gemm_tc<<<dim3(KVS / 128, MM / 128), 256, GSM_BYTES>>>(
        nh, nl, WkvTh, WkvTl, bk, bv, 1024, nullptr, nullptr,
        kvh, kvl, MM, KVS, EE, 0, 1.0f);
    // 6-7: MLP weight prep
    tsplit_kernel<<<dim3(FF / 32, EE / 32), 256>>>(W1, W1Th, W1Tl, EE, FF);
    tsplit_kernel<<<dim3(EE / 32, FF / 32), 256>>>(W2, W2Th, W2Tl, FF, EE);
    // 8: tensor-core causal attention + residual
    attn_mma<<<dim3(CC / 128, HH, BB), 256, ATTN_SMEM>>>(
        qh, ql, kvh, kvl, inputs, outbuf);
    // 9: LN2 -> bf16 pair
    ln_kernel<<<MM, 256>>>(outbuf, g2, beta2, hh, hl);
    // 10: MLP1 (relu) -> bf16 pair
    gemm_tc<<<dim3(FF / 128, MM / 128), 256, GSM_BYTES>>>(
        hh, hl, W1Th, W1Tl, bm1, nullptr, 0, nullptr, nullptr,
        m1h, m1l, MM, FF, EE, 1, 1.0f);
    // 11: MLP2 + residual -> out
    gemm_tc<<<dim3(EE / 128, MM / 128), 256, GSM_BYTES>>>(
        m1h, m1l, W2Th, W2Tl, bm2, nullptr, 0, outbuf, out,
        nullptr, nullptr, MM, EE, FF, 0, 1.0f);
}